// round 11
// baseline (speedup 1.0000x reference)
#include <cuda_runtime.h>
#include <cuda_fp16.h>
#include <cstdint>

// ============================================================================
// LSTMCell on GB300 via mma.sync (HMMA) — tcgen05 unavailable (compute_103 PTX).
// gates[B,512] = [x|h] @ Wcat^T, fp16 operands / fp32 accum, fused epilogue.
//
// R10 -> R11: back to 16 warps/SM (one 512-thread CTA, 2 mtiles/warp,
// ~110 regs/thread) while keeping: prepacked fragment-direct A (no barriers,
// no smem A), smem-resident W fragments, register prefetch of A and B,
// c_t gathered before the MUFU chain. Prepass fused into ONE kernel.
// ============================================================================

// Weights pre-packed in mma-fragment-ready layout with k-permutation pi:
//   frag j=0 holds k pairs (4l,4l+1), j=1 holds (4l+2,4l+3)
// addr = ks*4096 + ntp*512 + lane*16 + e*8 + j*4,  ntp = q*2 + g-half
__device__ __align__(16) unsigned char g_wb[4][65536];

// A fragments: uint4 per (mt, ks, mtile, lane):
//   idx = mt*8192 + ks*512 + mtile*32 + lane   (mt: 256-row tile)
//   w.x=(r,k4l..), w.y=(r+8,..), w.z=(r,k4l+2..), w.w=(r+8,..)
__device__ __align__(16) uint4 g_a[2097152];   // 32 MB

__device__ __forceinline__ uint32_t smem_u32(const void* p) {
    uint32_t a;
    asm("{ .reg .u64 t; cvta.to.shared.u64 t, %1; cvt.u32.u64 %0, t; }"
        : "=r"(a) : "l"(p));
    return a;
}

__device__ __forceinline__ float fast_sigmoid(float x) {
    float e, r;
    asm("ex2.approx.f32 %0, %1;" : "=f"(e) : "f"(-1.4426950408889634f * x));
    asm("rcp.approx.f32 %0, %1;" : "=f"(r) : "f"(1.0f + e));
    return r;
}
__device__ __forceinline__ float fast_tanh(float x) {
    float e, r;
    asm("ex2.approx.f32 %0, %1;" : "=f"(e) : "f"(2.8853900817779268f * x));
    asm("rcp.approx.f32 %0, %1;" : "=f"(r) : "f"(e + 1.0f));
    return 1.0f - 2.0f * r;   // handles +-inf correctly -> +-1
}

__device__ __forceinline__ uint32_t cvt_h2(float lo, float hi) {
    uint32_t r;
    asm("cvt.rn.f16x2.f32 %0, %1, %2;" : "=r"(r) : "f"(hi), "f"(lo));
    return r;
}

__device__ __forceinline__ void mma16816(float* d, const uint32_t* a,
                                         uint32_t b0, uint32_t b1) {
    asm volatile(
        "mma.sync.aligned.m16n8k16.row.col.f32.f16.f16.f32 "
        "{%0,%1,%2,%3}, {%4,%5,%6,%7}, {%8,%9}, {%0,%1,%2,%3};\n"
        : "+f"(d[0]), "+f"(d[1]), "+f"(d[2]), "+f"(d[3])
        : "r"(a[0]), "r"(a[1]), "r"(a[2]), "r"(a[3]), "r"(b0), "r"(b1));
}

__device__ __forceinline__ void lds128(uint32_t* r, uint32_t addr) {
    asm volatile("ld.shared.v4.b32 {%0,%1,%2,%3}, [%4];\n"
                 : "=r"(r[0]), "=r"(r[1]), "=r"(r[2]), "=r"(r[3]) : "r"(addr));
}

// ---------------- SMEM layout (dynamic) ----------------
static constexpr int SMEM_W  = 0;
static constexpr int SMEM_BS = 65536;
static constexpr int SMEM_TOTAL = SMEM_BS + 512;

// ============================================================================
// Kernel 0 (fused prepass): blocks [0, aBlocks) convert activations
// fp32 -> fp16 fragment-lane layout; blocks [aBlocks, aBlocks+256) pack W.
// ============================================================================
__global__ void __launch_bounds__(256)
prep_kernel(const float* __restrict__ x, const float* __restrict__ h,
            const float* __restrict__ Wii, const float* __restrict__ Whi,
            const float* __restrict__ Wif, const float* __restrict__ Whf,
            const float* __restrict__ Wig, const float* __restrict__ Whg,
            const float* __restrict__ Wio, const float* __restrict__ Who,
            int aBlocks)
{
    if (blockIdx.x < (unsigned)aBlocks) {
        // ---- activation convert: one thread = one 16B fragment lane ----
        const int idx   = blockIdx.x * 256 + threadIdx.x;
        const int lane  = idx & 31;
        const int mtile = (idx >> 5) & 15;
        const int ks    = (idx >> 9) & 15;
        const int mt    = idx >> 13;

        const int r = mt * 256 + mtile * 16 + (lane >> 2);
        const int k = ks * 16 + (lane & 3) * 4;
        const float* base = (k < 128) ? x : h;
        const int kk = k & 127;

        const float4 v = __ldg((const float4*)(base + (size_t)r * 128 + kk));
        const float4 u = __ldg((const float4*)(base + (size_t)(r + 8) * 128 + kk));

        uint4 w;
        w.x = cvt_h2(v.x, v.y);
        w.y = cvt_h2(u.x, u.y);
        w.z = cvt_h2(v.z, v.w);
        w.w = cvt_h2(u.z, u.w);
        g_a[idx] = w;
    } else {
        // ---- weight pack (256 blocks) ----
        int idx = (blockIdx.x - aBlocks) * 256 + threadIdx.x;  // 0..65535 pairs
        int gcol = idx >> 7;
        int kp   = idx & 127;
        int k    = kp * 2;

        int q    = gcol >> 7;
        int hcol = gcol & 127;
        int qh   = hcol >> 5;
        int hc   = hcol & 31;

        int t    = hc >> 3;
        int ntp  = q * 2 + (t >> 1);
        int e    = t & 1;
        int l    = (k >> 2) & 3;
        int j    = (k >> 1) & 1;
        int lane = (hc & 7) * 4 + l;
        int ks   = k >> 4;

        const float* Wx;
        const float* Wh;
        switch (q) {
            case 0:  Wx = Wii; Wh = Whi; break;
            case 1:  Wx = Wif; Wh = Whf; break;
            case 2:  Wx = Wig; Wh = Whg; break;
            default: Wx = Wio; Wh = Who; break;
        }
        float2 v;
        if (k < 128) v = ((const float2*)(Wx + hcol * 128))[kp];
        else         v = ((const float2*)(Wh + hcol * 128))[kp - 64];

        __half2 hv = __floats2half2_rn(v.x, v.y);
        *(uint32_t*)&g_wb[qh][(((ks * 8 + ntp) * 32 + lane) * 16) + e * 8 + j * 4]
            = *(uint32_t*)&hv;
    }
}

// ============================================================================
// Kernel 1: persistent GEMM + LSTM epilogue. grid=148 x 512 threads, 1 CTA/SM.
// blk&3 = qh (hcol quarter); blk>>2 (0..36) strides batch tiles of 256 rows.
// Warp w (16): mgroup = w&7 (mtiles 2mg, 2mg+1), g = w>>3 (ntp half).
// Barrier-free tile loop; A and B register-prefetched.
// ============================================================================
__global__ void __launch_bounds__(512, 1)
lstm_main_kernel(
    const float* __restrict__ c_t,
    const float* __restrict__ b_i, const float* __restrict__ b_f,
    const float* __restrict__ b_g, const float* __restrict__ b_o,
    float* __restrict__ out, int batch, int mt_total)
{
    extern __shared__ char smem[];
    const uint32_t sb = smem_u32(smem);
    const uint32_t sW = sb + SMEM_W;
    float* bs = (float*)(smem + SMEM_BS);

    const int tid  = threadIdx.x;
    const int wid  = tid >> 5;
    const int lane = tid & 31;
    const int qh   = blockIdx.x & 3;
    const int cta  = blockIdx.x >> 2;          // 0..36
    const int mt_stride = gridDim.x >> 2;      // 37

    const int mgroup = wid & 7;
    const int g      = wid >> 3;

    // ---- load W fragments (once) via cp.async: 512 thr x 16B x 8 = 64KB ----
    {
        const char* src = (const char*)&g_wb[qh][0] + tid * 16;
        uint32_t dst = sW + tid * 16;
        #pragma unroll
        for (int i = 0; i < 8; i++) {
            asm volatile("cp.async.ca.shared.global [%0], [%1], 16;\n"
                         :: "r"(dst + i * 8192), "l"(src + i * 8192));
        }
        asm volatile("cp.async.commit_group;\n" ::: "memory");
    }
    // ---- biases for this quarter: bs[q][hc] ----
    if (tid < 128) {
        int q  = tid >> 5;
        int hc = tid & 31;
        const float* bp = (q == 0) ? b_i : (q == 1) ? b_f : (q == 2) ? b_g : b_o;
        bs[tid] = bp[qh * 32 + hc];
    }
    asm volatile("cp.async.wait_group 0;\n" ::: "memory");
    __syncthreads();

    // ---- consumer geometry ----
    const uint32_t bLane = sW + (uint32_t)(g * 512 + lane * 16);
    const uint32_t aOff  = (uint32_t)(mgroup * 1024 + lane * 16);  // mtile=2mg
    const size_t cbase = (size_t)batch * 128;

    // ---- persistent tile loop (barrier-free) ----
    for (int mt = cta; mt < mt_total; mt += mt_stride) {

        float acc[2][4][2][4];                 // [mtile][gate][e][frag]
        #pragma unroll
        for (int a0 = 0; a0 < 2; a0++)
            #pragma unroll
            for (int a1 = 0; a1 < 4; a1++)
                #pragma unroll
                for (int a2 = 0; a2 < 2; a2++)
                    #pragma unroll
                    for (int a3 = 0; a3 < 4; a3++)
                        acc[a0][a1][a2][a3] = 0.0f;

        const char* aBase = (const char*)g_a + (size_t)mt * 131072 + aOff;

        uint4 Ac[2], An[2];
        Ac[0] = __ldg((const uint4*)(aBase));
        Ac[1] = __ldg((const uint4*)(aBase + 512));

        #pragma unroll
        for (int ks = 0; ks < 16; ks++) {
            // prefetch A for ks+1
            if (ks < 15) {
                const char* ap = aBase + (ks + 1) * 8192;
                An[0] = __ldg((const uint4*)(ap));
                An[1] = __ldg((const uint4*)(ap + 512));
            }

            // load all four B fragments for this ks up-front
            uint32_t B[4][4];
            const uint32_t bb = bLane + (uint32_t)(ks * 4096);
            #pragma unroll
            for (int q = 0; q < 4; q++)
                lds128(B[q], bb + (uint32_t)(q * 1024));

            #pragma unroll
            for (int q = 0; q < 4; q++) {
                #pragma unroll
                for (int m = 0; m < 2; m++) {
                    mma16816(acc[m][q][0], (const uint32_t*)&Ac[m], B[q][0], B[q][1]);
                    mma16816(acc[m][q][1], (const uint32_t*)&Ac[m], B[q][2], B[q][3]);
                }
            }

            Ac[0] = An[0];
            Ac[1] = An[1];
        }

        // ---- epilogue: gather c_t first, then MUFU chain, then stores ----
        const int hc0 = (g << 4) + ((lane & 3) << 1);  // e=0 col base within 32
        const int hcol0 = (qh << 5) + hc0;
        float2 cv[2][2][2];                    // [m][e][rh]
        #pragma unroll
        for (int m = 0; m < 2; m++) {
            const int rr0 = mt * 256 + (mgroup * 2 + m) * 16 + (lane >> 2);
            #pragma unroll
            for (int e = 0; e < 2; e++) {
                const int hcol = hcol0 + e * 8;
                cv[m][e][0] = __ldg((const float2*)(c_t + (size_t)rr0 * 128 + hcol));
                cv[m][e][1] = __ldg((const float2*)(c_t + (size_t)(rr0 + 8) * 128 + hcol));
            }
        }

        #pragma unroll
        for (int m = 0; m < 2; m++) {
            const int rr0 = mt * 256 + (mgroup * 2 + m) * 16 + (lane >> 2);
            #pragma unroll
            for (int e = 0; e < 2; e++) {
                const int hc32 = hc0 + e * 8;
                const int hcol = hcol0 + e * 8;
                const float bi0 = bs[hc32],      bi1 = bs[hc32 + 1];
                const float bf0 = bs[32 + hc32], bf1 = bs[32 + hc32 + 1];
                const float bg0 = bs[64 + hc32], bg1 = bs[64 + hc32 + 1];
                const float bo0 = bs[96 + hc32], bo1 = bs[96 + hc32 + 1];
                #pragma unroll
                for (int rh = 0; rh < 2; rh++) {
                    const int row = rr0 + rh * 8;
                    const float2 cc = cv[m][e][rh];

                    float ia0 = acc[m][0][e][rh * 2 + 0] + bi0;
                    float ia1 = acc[m][0][e][rh * 2 + 1] + bi1;
                    float fa0 = acc[m][1][e][rh * 2 + 0] + bf0;
                    float fa1 = acc[m][1][e][rh * 2 + 1] + bf1;
                    float ga0 = acc[m][2][e][rh * 2 + 0] + bg0;
                    float ga1 = acc[m][2][e][rh * 2 + 1] + bg1;
                    float oa0 = acc[m][3][e][rh * 2 + 0] + bo0;
                    float oa1 = acc[m][3][e][rh * 2 + 1] + bo1;

                    float it0 = fast_sigmoid(ia0), it1 = fast_sigmoid(ia1);
                    float ft0 = fast_sigmoid(fa0), ft1 = fast_sigmoid(fa1);
                    float gt0 = fast_tanh(ga0),    gt1 = fast_tanh(ga1);
                    float ot0 = fast_sigmoid(oa0), ot1 = fast_sigmoid(oa1);

                    float cn0 = ft0 * cc.x + it0 * gt0;
                    float cn1 = ft1 * cc.y + it1 * gt1;
                    float hn0 = ot0 * fast_tanh(cn0);
                    float hn1 = ot1 * fast_tanh(cn1);

                    float2 ho = make_float2(hn0, hn1);
                    float2 co = make_float2(cn0, cn1);
                    *(float2*)(out + (size_t)row * 128 + hcol) = ho;
                    *(float2*)(out + cbase + (size_t)row * 128 + hcol) = co;
                }
            }
        }
    }
}

// ============================================================================
// Host launch
// ============================================================================
extern "C" void kernel_launch(void* const* d_in, const int* in_sizes, int n_in,
                              void* d_out, int out_size)
{
    (void)n_in; (void)out_size;
    const float* x   = (const float*)d_in[0];
    const float* h_t = (const float*)d_in[1];
    const float* c_t = (const float*)d_in[2];
    const float* Wii = (const float*)d_in[3];
    const float* Whi = (const float*)d_in[4];
    const float* b_i = (const float*)d_in[5];
    const float* Wif = (const float*)d_in[6];
    const float* Whf = (const float*)d_in[7];
    const float* b_f = (const float*)d_in[8];
    const float* Wig = (const float*)d_in[9];
    const float* Whg = (const float*)d_in[10];
    const float* b_g = (const float*)d_in[11];
    const float* Wio = (const float*)d_in[12];
    const float* Who = (const float*)d_in[13];
    const float* b_o = (const float*)d_in[14];

    const int batch    = in_sizes[0] / 128;
    const int mt_total = batch / 256;
    const int aBlocks  = mt_total * 32;        // 8192 for batch 65536

    prep_kernel<<<aBlocks + 256, 256>>>(x, h_t, Wii, Whi, Wif, Whf,
                                        Wig, Whg, Wio, Who, aBlocks);

    static bool attr_set = false;
    if (!attr_set) {
        cudaFuncSetAttribute(lstm_main_kernel,
                             cudaFuncAttributeMaxDynamicSharedMemorySize,
                             SMEM_TOTAL);
        attr_set = true;
    }
    lstm_main_kernel<<<148, 512, SMEM_TOTAL>>>(
        c_t, b_i, b_f, b_g, b_o, (float*)d_out, batch, mt_total);
}

// round 12
// speedup vs baseline: 1.3943x; 1.3943x over previous
#include <cuda_runtime.h>
#include <cuda_fp16.h>
#include <cstdint>

// ============================================================================
// LSTMCell on GB300 via mma.sync (HMMA) — tcgen05 unavailable (compute_103 PTX).
// gates[B,512] = [x|h] @ Wcat^T, fp16 operands / fp32 accum, fused epilogue.
//
// R11 -> R12:
//  - tanh.approx.f32 for all activations (MUFU per element 10 -> 5)
//  - prepass: 512-thr blocks, 4 fragment lanes/thread (1024+128 blocks)
//  - .cs streaming hints on c_t loads and output stores (protect g_a in L2)
// Main GEMM structure unchanged: 148 x 512thr, 16 warps/SM, 2 mtiles/warp,
// prepacked fragment-direct A, barrier-free tile loop.
// ============================================================================

// Weights pre-packed in mma-fragment-ready layout with k-permutation pi:
//   frag j=0 holds k pairs (4l,4l+1), j=1 holds (4l+2,4l+3)
// addr = ks*4096 + ntp*512 + lane*16 + e*8 + j*4,  ntp = q*2 + g-half
__device__ __align__(16) unsigned char g_wb[4][65536];

// A fragments: uint4 per (mt, ks, mtile, lane):
//   idx = mt*8192 + ks*512 + mtile*32 + lane   (mt: 256-row tile)
__device__ __align__(16) uint4 g_a[2097152];   // 32 MB

__device__ __forceinline__ uint32_t smem_u32(const void* p) {
    uint32_t a;
    asm("{ .reg .u64 t; cvta.to.shared.u64 t, %1; cvt.u32.u64 %0, t; }"
        : "=r"(a) : "l"(p));
    return a;
}

__device__ __forceinline__ float fast_tanh(float x) {
    float r;
    asm("tanh.approx.f32 %0, %1;" : "=f"(r) : "f"(x));
    return r;
}
__device__ __forceinline__ float fast_sigmoid(float x) {
    return fmaf(0.5f, fast_tanh(0.5f * x), 0.5f);
}

__device__ __forceinline__ uint32_t cvt_h2(float lo, float hi) {
    uint32_t r;
    asm("cvt.rn.f16x2.f32 %0, %1, %2;" : "=r"(r) : "f"(hi), "f"(lo));
    return r;
}

__device__ __forceinline__ void mma16816(float* d, const uint32_t* a,
                                         uint32_t b0, uint32_t b1) {
    asm volatile(
        "mma.sync.aligned.m16n8k16.row.col.f32.f16.f16.f32 "
        "{%0,%1,%2,%3}, {%4,%5,%6,%7}, {%8,%9}, {%0,%1,%2,%3};\n"
        : "+f"(d[0]), "+f"(d[1]), "+f"(d[2]), "+f"(d[3])
        : "r"(a[0]), "r"(a[1]), "r"(a[2]), "r"(a[3]), "r"(b0), "r"(b1));
}

__device__ __forceinline__ void lds128(uint32_t* r, uint32_t addr) {
    asm volatile("ld.shared.v4.b32 {%0,%1,%2,%3}, [%4];\n"
                 : "=r"(r[0]), "=r"(r[1]), "=r"(r[2]), "=r"(r[3]) : "r"(addr));
}

__device__ __forceinline__ float2 ldg_cs_f2(const float* p) {
    float2 v;
    asm volatile("ld.global.cs.v2.f32 {%0,%1}, [%2];\n"
                 : "=f"(v.x), "=f"(v.y) : "l"(p));
    return v;
}
__device__ __forceinline__ void stg_cs_f2(float* p, float a, float b) {
    asm volatile("st.global.cs.v2.f32 [%0], {%1,%2};\n"
                 :: "l"(p), "f"(a), "f"(b));
}

// ---------------- SMEM layout (dynamic) ----------------
static constexpr int SMEM_W  = 0;
static constexpr int SMEM_BS = 65536;
static constexpr int SMEM_TOTAL = SMEM_BS + 512;

// ============================================================================
// Kernel 0 (fused prepass, 512-thr blocks):
//   blocks [0, aBlocks): activation convert, 4 fragment lanes per thread
//   blocks [aBlocks, aBlocks+128): weight pack
// ============================================================================
__global__ void __launch_bounds__(512)
prep_kernel(const float* __restrict__ x, const float* __restrict__ h,
            const float* __restrict__ Wii, const float* __restrict__ Whi,
            const float* __restrict__ Wif, const float* __restrict__ Whf,
            const float* __restrict__ Wig, const float* __restrict__ Whg,
            const float* __restrict__ Wio, const float* __restrict__ Who,
            int aBlocks)
{
    if (blockIdx.x < (unsigned)aBlocks) {
        const int base = blockIdx.x * 2048 + threadIdx.x;
        #pragma unroll
        for (int i = 0; i < 4; i++) {
            const int idx   = base + i * 512;
            const int lane  = idx & 31;
            const int mtile = (idx >> 5) & 15;
            const int ks    = (idx >> 9) & 15;
            const int mt    = idx >> 13;

            const int r = mt * 256 + mtile * 16 + (lane >> 2);
            const int k = ks * 16 + (lane & 3) * 4;
            const float* bsrc = (k < 128) ? x : h;
            const int kk = k & 127;

            const float4 v = __ldg((const float4*)(bsrc + (size_t)r * 128 + kk));
            const float4 u = __ldg((const float4*)(bsrc + (size_t)(r + 8) * 128 + kk));

            uint4 w;
            w.x = cvt_h2(v.x, v.y);
            w.y = cvt_h2(u.x, u.y);
            w.z = cvt_h2(v.z, v.w);
            w.w = cvt_h2(u.z, u.w);
            g_a[idx] = w;
        }
    } else {
        int idx = (blockIdx.x - aBlocks) * 512 + threadIdx.x;  // 0..65535 pairs
        int gcol = idx >> 7;
        int kp   = idx & 127;
        int k    = kp * 2;

        int q    = gcol >> 7;
        int hcol = gcol & 127;
        int qh   = hcol >> 5;
        int hc   = hcol & 31;

        int t    = hc >> 3;
        int ntp  = q * 2 + (t >> 1);
        int e    = t & 1;
        int l    = (k >> 2) & 3;
        int j    = (k >> 1) & 1;
        int lane = (hc & 7) * 4 + l;
        int ks   = k >> 4;

        const float* Wx;
        const float* Wh;
        switch (q) {
            case 0:  Wx = Wii; Wh = Whi; break;
            case 1:  Wx = Wif; Wh = Whf; break;
            case 2:  Wx = Wig; Wh = Whg; break;
            default: Wx = Wio; Wh = Who; break;
        }
        float2 v;
        if (k < 128) v = ((const float2*)(Wx + hcol * 128))[kp];
        else         v = ((const float2*)(Wh + hcol * 128))[kp - 64];

        __half2 hv = __floats2half2_rn(v.x, v.y);
        *(uint32_t*)&g_wb[qh][(((ks * 8 + ntp) * 32 + lane) * 16) + e * 8 + j * 4]
            = *(uint32_t*)&hv;
    }
}

// ============================================================================
// Kernel 1: persistent GEMM + LSTM epilogue. grid=148 x 512 threads, 1 CTA/SM.
// blk&3 = qh (hcol quarter); blk>>2 (0..36) strides batch tiles of 256 rows.
// Warp w (16): mgroup = w&7 (mtiles 2mg, 2mg+1), g = w>>3 (ntp half).
// Barrier-free tile loop; A and B register-prefetched.
// ============================================================================
__global__ void __launch_bounds__(512, 1)
lstm_main_kernel(
    const float* __restrict__ c_t,
    const float* __restrict__ b_i, const float* __restrict__ b_f,
    const float* __restrict__ b_g, const float* __restrict__ b_o,
    float* __restrict__ out, int batch, int mt_total)
{
    extern __shared__ char smem[];
    const uint32_t sb = smem_u32(smem);
    const uint32_t sW = sb + SMEM_W;
    float* bs = (float*)(smem + SMEM_BS);

    const int tid  = threadIdx.x;
    const int wid  = tid >> 5;
    const int lane = tid & 31;
    const int qh   = blockIdx.x & 3;
    const int cta  = blockIdx.x >> 2;          // 0..36
    const int mt_stride = gridDim.x >> 2;      // 37

    const int mgroup = wid & 7;
    const int g      = wid >> 3;

    // ---- load W fragments (once) via cp.async: 512 thr x 16B x 8 = 64KB ----
    {
        const char* src = (const char*)&g_wb[qh][0] + tid * 16;
        uint32_t dst = sW + tid * 16;
        #pragma unroll
        for (int i = 0; i < 8; i++) {
            asm volatile("cp.async.ca.shared.global [%0], [%1], 16;\n"
                         :: "r"(dst + i * 8192), "l"(src + i * 8192));
        }
        asm volatile("cp.async.commit_group;\n" ::: "memory");
    }
    // ---- biases for this quarter: bs[q][hc] ----
    if (tid < 128) {
        int q  = tid >> 5;
        int hc = tid & 31;
        const float* bp = (q == 0) ? b_i : (q == 1) ? b_f : (q == 2) ? b_g : b_o;
        bs[tid] = bp[qh * 32 + hc];
    }
    asm volatile("cp.async.wait_group 0;\n" ::: "memory");
    __syncthreads();

    // ---- consumer geometry ----
    const uint32_t bLane = sW + (uint32_t)(g * 512 + lane * 16);
    const uint32_t aOff  = (uint32_t)(mgroup * 1024 + lane * 16);  // mtile=2mg
    const size_t cbase = (size_t)batch * 128;

    // ---- persistent tile loop (barrier-free) ----
    for (int mt = cta; mt < mt_total; mt += mt_stride) {

        float acc[2][4][2][4];                 // [mtile][gate][e][frag]
        #pragma unroll
        for (int a0 = 0; a0 < 2; a0++)
            #pragma unroll
            for (int a1 = 0; a1 < 4; a1++)
                #pragma unroll
                for (int a2 = 0; a2 < 2; a2++)
                    #pragma unroll
                    for (int a3 = 0; a3 < 4; a3++)
                        acc[a0][a1][a2][a3] = 0.0f;

        const char* aBase = (const char*)g_a + (size_t)mt * 131072 + aOff;

        uint4 Ac[2], An[2];
        Ac[0] = __ldg((const uint4*)(aBase));
        Ac[1] = __ldg((const uint4*)(aBase + 512));

        #pragma unroll
        for (int ks = 0; ks < 16; ks++) {
            // prefetch A for ks+1
            if (ks < 15) {
                const char* ap = aBase + (ks + 1) * 8192;
                An[0] = __ldg((const uint4*)(ap));
                An[1] = __ldg((const uint4*)(ap + 512));
            }

            // load all four B fragments for this ks up-front
            uint32_t B[4][4];
            const uint32_t bb = bLane + (uint32_t)(ks * 4096);
            #pragma unroll
            for (int q = 0; q < 4; q++)
                lds128(B[q], bb + (uint32_t)(q * 1024));

            #pragma unroll
            for (int q = 0; q < 4; q++) {
                #pragma unroll
                for (int m = 0; m < 2; m++) {
                    mma16816(acc[m][q][0], (const uint32_t*)&Ac[m], B[q][0], B[q][1]);
                    mma16816(acc[m][q][1], (const uint32_t*)&Ac[m], B[q][2], B[q][3]);
                }
            }

            Ac[0] = An[0];
            Ac[1] = An[1];
        }

        // ---- epilogue: gather c_t first, then tanh chain, then stores ----
        const int hc0 = (g << 4) + ((lane & 3) << 1);  // e=0 col base within 32
        const int hcol0 = (qh << 5) + hc0;
        float2 cv[2][2][2];                    // [m][e][rh]
        #pragma unroll
        for (int m = 0; m < 2; m++) {
            const int rr0 = mt * 256 + (mgroup * 2 + m) * 16 + (lane >> 2);
            #pragma unroll
            for (int e = 0; e < 2; e++) {
                const int hcol = hcol0 + e * 8;
                cv[m][e][0] = ldg_cs_f2(c_t + (size_t)rr0 * 128 + hcol);
                cv[m][e][1] = ldg_cs_f2(c_t + (size_t)(rr0 + 8) * 128 + hcol);
            }
        }

        #pragma unroll
        for (int m = 0; m < 2; m++) {
            const int rr0 = mt * 256 + (mgroup * 2 + m) * 16 + (lane >> 2);
            #pragma unroll
            for (int e = 0; e < 2; e++) {
                const int hc32 = hc0 + e * 8;
                const int hcol = hcol0 + e * 8;
                const float bi0 = bs[hc32],      bi1 = bs[hc32 + 1];
                const float bf0 = bs[32 + hc32], bf1 = bs[32 + hc32 + 1];
                const float bg0 = bs[64 + hc32], bg1 = bs[64 + hc32 + 1];
                const float bo0 = bs[96 + hc32], bo1 = bs[96 + hc32 + 1];
                #pragma unroll
                for (int rh = 0; rh < 2; rh++) {
                    const int row = rr0 + rh * 8;
                    const float2 cc = cv[m][e][rh];

                    float ia0 = acc[m][0][e][rh * 2 + 0] + bi0;
                    float ia1 = acc[m][0][e][rh * 2 + 1] + bi1;
                    float fa0 = acc[m][1][e][rh * 2 + 0] + bf0;
                    float fa1 = acc[m][1][e][rh * 2 + 1] + bf1;
                    float ga0 = acc[m][2][e][rh * 2 + 0] + bg0;
                    float ga1 = acc[m][2][e][rh * 2 + 1] + bg1;
                    float oa0 = acc[m][3][e][rh * 2 + 0] + bo0;
                    float oa1 = acc[m][3][e][rh * 2 + 1] + bo1;

                    float it0 = fast_sigmoid(ia0), it1 = fast_sigmoid(ia1);
                    float ft0 = fast_sigmoid(fa0), ft1 = fast_sigmoid(fa1);
                    float gt0 = fast_tanh(ga0),    gt1 = fast_tanh(ga1);
                    float ot0 = fast_sigmoid(oa0), ot1 = fast_sigmoid(oa1);

                    float cn0 = ft0 * cc.x + it0 * gt0;
                    float cn1 = ft1 * cc.y + it1 * gt1;
                    float hn0 = ot0 * fast_tanh(cn0);
                    float hn1 = ot1 * fast_tanh(cn1);

                    stg_cs_f2(out + (size_t)row * 128 + hcol, hn0, hn1);
                    stg_cs_f2(out + cbase + (size_t)row * 128 + hcol, cn0, cn1);
                }
            }
        }
    }
}

// ============================================================================
// Host launch
// ============================================================================
extern "C" void kernel_launch(void* const* d_in, const int* in_sizes, int n_in,
                              void* d_out, int out_size)
{
    (void)n_in; (void)out_size;
    const float* x   = (const float*)d_in[0];
    const float* h_t = (const float*)d_in[1];
    const float* c_t = (const float*)d_in[2];
    const float* Wii = (const float*)d_in[3];
    const float* Whi = (const float*)d_in[4];
    const float* b_i = (const float*)d_in[5];
    const float* Wif = (const float*)d_in[6];
    const float* Whf = (const float*)d_in[7];
    const float* b_f = (const float*)d_in[8];
    const float* Wig = (const float*)d_in[9];
    const float* Whg = (const float*)d_in[10];
    const float* b_g = (const float*)d_in[11];
    const float* Wio = (const float*)d_in[12];
    const float* Who = (const float*)d_in[13];
    const float* b_o = (const float*)d_in[14];

    const int batch    = in_sizes[0] / 128;
    const int mt_total = batch / 256;
    const int aBlocks  = mt_total * 4;         // 1024 for batch 65536

    prep_kernel<<<aBlocks + 128, 512>>>(x, h_t, Wii, Whi, Wif, Whf,
                                        Wig, Whg, Wio, Who, aBlocks);

    static bool attr_set = false;
    if (!attr_set) {
        cudaFuncSetAttribute(lstm_main_kernel,
                             cudaFuncAttributeMaxDynamicSharedMemorySize,
                             SMEM_TOTAL);
        attr_set = true;
    }
    lstm_main_kernel<<<148, 512, SMEM_TOTAL>>>(
        c_t, b_i, b_f, b_g, b_o, (float*)d_out, batch, mt_total);
}